// round 1
// baseline (speedup 1.0000x reference)
#include <cuda_runtime.h>
#include <cuda_bf16.h>

// Problem constants (fixed-shape problem)
#define H_DIM   1024
#define N_DIM   64
#define SEQ_L   2048
#define CHUNK   64                 // l-values per K2 thread
#define NCHUNK  (SEQ_L / CHUNK)    // 32

// Scratch (allocation-free rule: __device__ globals)
// params: per (h,n): {p2 = 2*Re(r^2), q2 = -|r|^4}
__device__ float2 g_params[H_DIM * N_DIM];
// seeds: per (h,n,chunk): {y0,y1,y2,y3} = Re(2*Ct * r^(64*chunk + m)), m=0..3
// padded by 64 so K2's unconditional prefetch of n+2/n+3 never reads OOB
__device__ float4 g_seeds[H_DIM * N_DIM * NCHUNK + 64];

// ---- packed f32x2 helpers (FFMA2 only reachable via PTX) ----
typedef unsigned long long ull;
__device__ __forceinline__ ull pack2(float lo, float hi) {
    ull r; asm("mov.b64 %0, {%1, %2};" : "=l"(r) : "f"(lo), "f"(hi)); return r;
}
__device__ __forceinline__ ull fma2(ull a, ull b, ull c) {
    ull d; asm("fma.rn.f32x2 %0, %1, %2, %3;" : "=l"(d) : "l"(a), "l"(b), "l"(c)); return d;
}
__device__ __forceinline__ ull mul2(ull a, ull b) {
    ull d; asm("mul.rn.f32x2 %0, %1, %2;" : "=l"(d) : "l"(a), "l"(b)); return d;
}
__device__ __forceinline__ ull add2(ull a, ull b) {
    ull d; asm("add.rn.f32x2 %0, %1, %2;" : "=l"(d) : "l"(a), "l"(b)); return d;
}

// ============================================================================
// K1: per (h,n) compute discretized params and per-chunk seeds.
//   dt   = exp(log_dt[h])
//   A    = -exp(inv_A_real) + i*A_imag ;  z = A*dt
//   den  = 1 - z/2   (Re(den) >= 1, never 0)
//   Ct2  = 2 * B*C*dt / den
//   r    = (1 + z/2) / den               (|r| < 1)
//   p2   = 2*Re(r^2), q2 = -|r|^4
//   seeds(chunk): y_m = Re(Ct2 * r^(64*chunk+m)), m = 0..3  (march w by r^64)
// ============================================================================
__global__ void __launch_bounds__(256) k1_precompute(
    const float* __restrict__ Cri, const float* __restrict__ logdt,
    const float* __restrict__ Bri, const float* __restrict__ invAr,
    const float* __restrict__ Aim)
{
    int idx = blockIdx.x * 256 + threadIdx.x;     // 0 .. 65535
    int h = idx >> 6;

    float cr = Cri[2 * idx], ci = Cri[2 * idx + 1];
    float br = Bri[2 * idx], bi = Bri[2 * idx + 1];
    float dt = __expf(logdt[h]);
    float Ar = -__expf(invAr[idx]);
    float Ai = Aim[idx];

    float zr = Ar * dt, zi = Ai * dt;
    float dr = 1.0f - 0.5f * zr, di = -0.5f * zi;
    float inv = 1.0f / (dr * dr + di * di);

    float bcr = br * cr - bi * ci;
    float bci = br * ci + bi * cr;
    float s = 2.0f * dt * inv;                     // fold the final 2x here
    float ctr = (bcr * dr + bci * di) * s;
    float cti = (bci * dr - bcr * di) * s;

    float nr = 1.0f + 0.5f * zr, ni = 0.5f * zi;
    float rr = (nr * dr + ni * di) * inv;
    float ri = (ni * dr - nr * di) * inv;

    float m2  = rr * rr + ri * ri;                 // |r|^2
    float r2r = rr * rr - ri * ri;
    float r2i = 2.0f * rr * ri;
    g_params[idx] = make_float2(2.0f * r2r, -(m2 * m2));

    // r^64 = (r^2)^(2^5) via 5 squarings
    float sr = r2r, si = r2i;
#pragma unroll
    for (int i = 0; i < 5; i++) {
        float tr = sr * sr - si * si;
        si = 2.0f * sr * si;
        sr = tr;
    }

    float wr = ctr, wi = cti;                      // w = Ct2 * r^(64*chunk)
    float4* sp = g_seeds + (size_t)idx * NCHUNK;
#pragma unroll 1
    for (int c = 0; c < NCHUNK; c++) {
        float w1r = wr * rr - wi * ri, w1i = wr * ri + wi * rr;   // w*r
        float w2r = w1r * rr - w1i * ri, w2i = w1r * ri + w1i * rr; // w*r^2
        float w3r = w2r * rr - w2i * ri;                          // Re(w*r^3)
        sp[c] = make_float4(wr, w1r, w2r, w3r);
        float tr = wr * sr - wi * si;                             // w *= r^64
        wi = wr * si + wi * sr;
        wr = tr;
    }
}

// ============================================================================
// K2: one thread per (h, chunk). 32 packed accumulators (y_{2k}, y_{2k+1}).
// Order-2 stride-2 recurrence, two n-streams interleaved for ILP, seeds
// prefetched one n-pair ahead. All hot math on the fma pipe as f32x2.
// ============================================================================
__global__ void __launch_bounds__(64) k2_vandermonde(float* __restrict__ out)
{
    const int tx = threadIdx.x;            // chunk 0..31
    const int ty = threadIdx.y;            // 0..1 (h within block)
    const int h  = blockIdx.x * 2 + ty;

    __shared__ float2 sp[2][N_DIM];
    {
        int tid = ty * 32 + tx;            // 0..63
        const float2* gp = g_params + (size_t)blockIdx.x * 2 * N_DIM;
        ((float2*)sp)[tid]      = gp[tid];
        ((float2*)sp)[tid + 64] = gp[tid + 64];
    }
    __syncthreads();

    ull acc[CHUNK / 2];
#pragma unroll
    for (int k = 0; k < CHUNK / 2; k++) acc[k] = 0ull;

    const float4* sbase = g_seeds + (size_t)h * N_DIM * NCHUNK + tx;
    float4 sa = sbase[0];
    float4 sb = sbase[NCHUNK];

#pragma unroll 1
    for (int n = 0; n < N_DIM; n += 2) {
        // prefetch next pair (padding makes the final read safe)
        float4 pa = sbase[(size_t)(n + 2) * NCHUNK];
        float4 pb = sbase[(size_t)(n + 3) * NCHUNK];

        float2 qa = sp[ty][n];
        float2 qb = sp[ty][n + 1];
        ull p2a = pack2(qa.x, qa.x), q2a = pack2(qa.y, qa.y);
        ull p2b = pack2(qb.x, qb.x), q2b = pack2(qb.y, qb.y);

        ull vpA = pack2(sa.x, sa.y), vcA = pack2(sa.z, sa.w);
        ull vpB = pack2(sb.x, sb.y), vcB = pack2(sb.z, sb.w);

        acc[0] = add2(acc[0], add2(vpA, vpB));
        acc[1] = add2(acc[1], add2(vcA, vcB));

#pragma unroll
        for (int k = 2; k < CHUNK / 2; k++) {
            ull nA = fma2(p2a, vcA, mul2(q2a, vpA));
            ull nB = fma2(p2b, vcB, mul2(q2b, vpB));
            acc[k] = add2(acc[k], add2(nA, nB));
            vpA = vcA; vcA = nA;
            vpB = vcB; vcB = nB;
        }
        sa = pa; sb = pb;
    }

    // out[h, tx*64 + 2k .. 2k+1]; 16B-aligned -> STG.128 pairs
    ulonglong2* op = (ulonglong2*)(out + (size_t)h * SEQ_L + tx * CHUNK);
#pragma unroll
    for (int k = 0; k < CHUNK / 4; k++)
        op[k] = make_ulonglong2(acc[2 * k], acc[2 * k + 1]);
}

extern "C" void kernel_launch(void* const* d_in, const int* in_sizes, int n_in,
                              void* d_out, int out_size)
{
    const float* Cri   = (const float*)d_in[0];   // (1, H, N, 2)
    const float* logdt = (const float*)d_in[1];   // (H,)
    const float* Bri   = (const float*)d_in[2];   // (H, N, 2)  (n_ssm == H)
    const float* invAr = (const float*)d_in[3];   // (H, N)
    const float* Aim   = (const float*)d_in[4];   // (H, N)
    float* out = (float*)d_out;                   // (1, H, L)

    k1_precompute<<<(H_DIM * N_DIM) / 256, 256>>>(Cri, logdt, Bri, invAr, Aim);

    dim3 blk(32, 2);
    k2_vandermonde<<<H_DIM / 2, blk>>>(out);
}

// round 2
// speedup vs baseline: 1.8611x; 1.8611x over previous
#include <cuda_runtime.h>
#include <cuda_bf16.h>

// Fixed shapes
#define H_DIM   1024
#define N_DIM   64
#define SEQ_L   2048
#define CHUNK   64                 // l-values per (h, chunk) column
#define NCHUNK  (SEQ_L / CHUNK)    // 32 chunks
#define NQ      4                  // n-quarters per chunk (reduction ways)

typedef unsigned long long ull;
__device__ __forceinline__ ull pack2(float lo, float hi) {
    ull r; asm("mov.b64 %0, {%1, %2};" : "=l"(r) : "f"(lo), "f"(hi)); return r;
}
__device__ __forceinline__ ull fma2(ull a, ull b, ull c) {
    ull d; asm("fma.rn.f32x2 %0, %1, %2, %3;" : "=l"(d) : "l"(a), "l"(b), "l"(c)); return d;
}
__device__ __forceinline__ ull mul2(ull a, ull b) {
    ull d; asm("mul.rn.f32x2 %0, %1, %2;" : "=l"(d) : "l"(a), "l"(b)); return d;
}
__device__ __forceinline__ ull add2(ull a, ull b) {
    ull d; asm("add.rn.f32x2 %0, %1, %2;" : "=l"(d) : "l"(a), "l"(b)); return d;
}

// ============================================================================
// Fused kernel: one block per h, 128 threads (4 warps).
// Phase 1: 128 threads = (n 0..63) x (half 0..1). Each computes discretized
//   params for its n and marches 16 chunk-seeds (y0,y1) into smem.
//   half=1 starts at r^1024 via 4 extra squarings of r^64.
// Phase 2: 128 threads = (chunk c 0..31) x (quarter q 0..3). Each runs the
//   packed stride-2 recurrence over 16 n (2 interleaved streams), 32 packed
//   accumulators covering l = c*64 .. c*64+63.
// Phase 3: 4-way reduction over quarters via smem (seeds region reused),
//   warp 0 stores the h-row.
// ============================================================================
__global__ void __launch_bounds__(128) ssk_fused(
    const float* __restrict__ Cri, const float* __restrict__ logdt,
    const float* __restrict__ Bri, const float* __restrict__ invAr,
    const float* __restrict__ Aim, float* __restrict__ out)
{
    __shared__ float2 s_seed[N_DIM * NCHUNK];   // 16KB, [n][c ^ (n&31)]
    __shared__ float4 s_par[N_DIM];             // 1KB, (p1, q1, p2, q2)

    const int tx = threadIdx.x;                 // 0..127
    const int h  = blockIdx.x;

    // ---------------- Phase 1: params + seeds ----------------
    {
        const int n    = tx & 63;
        const int half = tx >> 6;
        const int idx  = h * N_DIM + n;

        float cr = Cri[2 * idx], ci = Cri[2 * idx + 1];
        float br = Bri[2 * idx], bi = Bri[2 * idx + 1];
        float dt = __expf(logdt[h]);
        float Ar = -__expf(invAr[idx]);
        float Ai = Aim[idx];

        float zr = Ar * dt, zi = Ai * dt;
        float dr = 1.0f - 0.5f * zr, di = -0.5f * zi;
        float inv = 1.0f / (dr * dr + di * di);

        float bcr = br * cr - bi * ci;
        float bci = br * ci + bi * cr;
        float s = 2.0f * dt * inv;
        float ctr = (bcr * dr + bci * di) * s;   // Ct2 = 2*B*C*dt/den
        float cti = (bci * dr - bcr * di) * s;

        float nr = 1.0f + 0.5f * zr, ni = 0.5f * zi;
        float rr = (nr * dr + ni * di) * inv;    // r, |r| < 1
        float ri = (ni * dr - nr * di) * inv;

        float m2  = rr * rr + ri * ri;           // |r|^2
        float r2r = rr * rr - ri * ri;
        float r2i = 2.0f * rr * ri;
        if (half == 0)
            s_par[n] = make_float4(2.0f * rr, -m2, 2.0f * r2r, -(m2 * m2));

        // r^64 = (r^2)^32 : 5 squarings
        float sr = r2r, si = r2i;
#pragma unroll
        for (int i = 0; i < 5; i++) {
            float tr = sr * sr - si * si;
            si = 2.0f * sr * si;
            sr = tr;
        }

        float wr = ctr, wi = cti;                // w = Ct2 * r^(64*chunk)
        if (half) {
            // r^1024 = (r^64)^16 : 4 squarings
            float pr = sr, pi = si;
#pragma unroll
            for (int i = 0; i < 4; i++) {
                float tr = pr * pr - pi * pi;
                pi = 2.0f * pr * pi;
                pr = tr;
            }
            float tr = wr * pr - wi * pi;
            wi = wr * pi + wi * pr;
            wr = tr;
        }

        int cbase = half * 16;
#pragma unroll 1
        for (int i = 0; i < 16; i++) {
            int c = cbase + i;
            float y1 = wr * rr - wi * ri;        // Re(w * r)
            s_seed[n * NCHUNK + (c ^ (n & 31))] = make_float2(wr, y1);
            float tr = wr * sr - wi * si;        // w *= r^64
            wi = wr * si + wi * sr;
            wr = tr;
        }
    }
    __syncthreads();

    // ---------------- Phase 2: packed recurrence ----------------
    const int c = tx & 31;                       // chunk (lane within warp)
    const int q = tx >> 5;                       // quarter (warp id)

    ull acc[CHUNK / 2];
#pragma unroll
    for (int k = 0; k < CHUNK / 2; k++) acc[k] = 0ull;

    const int n0 = q * 16;
#pragma unroll 1
    for (int np = 0; np < 8; np++) {
        const int na = n0 + 2 * np;
        const int nb = na + 1;

        float4 pa = s_par[na];
        float4 pb = s_par[nb];
        float2 sa = s_seed[na * NCHUNK + (c ^ (na & 31))];
        float2 sb = s_seed[nb * NCHUNK + (c ^ (nb & 31))];

        // reconstruct y2,y3 via stride-1 recurrence
        float y2a = fmaf(pa.x, sa.y, pa.y * sa.x);
        float y3a = fmaf(pa.x, y2a, pa.y * sa.y);
        float y2b = fmaf(pb.x, sb.y, pb.y * sb.x);
        float y3b = fmaf(pb.x, y2b, pb.y * sb.y);

        ull p2a = pack2(pa.z, pa.z), q2a = pack2(pa.w, pa.w);
        ull p2b = pack2(pb.z, pb.z), q2b = pack2(pb.w, pb.w);

        ull vpA = pack2(sa.x, sa.y), vcA = pack2(y2a, y3a);
        ull vpB = pack2(sb.x, sb.y), vcB = pack2(y2b, y3b);

        acc[0] = add2(acc[0], add2(vpA, vpB));
        acc[1] = add2(acc[1], add2(vcA, vcB));

#pragma unroll
        for (int k = 2; k < CHUNK / 2; k++) {
            ull nA = fma2(p2a, vcA, mul2(q2a, vpA));
            ull nB = fma2(p2b, vcB, mul2(q2b, vpB));
            acc[k] = add2(acc[k], add2(nA, nB));
            vpA = vcA; vcA = nA;
            vpB = vcB; vcB = nB;
        }
    }

    // ---------------- Phase 3: 4-way reduction, warp 0 stores ----------------
    __syncthreads();                              // seeds no longer needed
    ull* red = (ull*)s_seed;                      // reuse 16KB region

    // Round A: quarters 2,3 publish; 0,1 absorb.
    if (q >= 2) {
#pragma unroll
        for (int k = 0; k < CHUNK / 2; k++)
            red[k * 64 + (q - 2) * 32 + c] = acc[k];
    }
    __syncthreads();
    if (q < 2) {
#pragma unroll
        for (int k = 0; k < CHUNK / 2; k++)
            acc[k] = add2(acc[k], red[k * 64 + q * 32 + c]);
    }
    __syncthreads();
    // Round B: quarter 1 publishes; 0 absorbs and stores.
    if (q == 1) {
#pragma unroll
        for (int k = 0; k < CHUNK / 2; k++)
            red[k * 32 + c] = acc[k];
    }
    __syncthreads();
    if (q == 0) {
#pragma unroll
        for (int k = 0; k < CHUNK / 2; k++)
            acc[k] = add2(acc[k], red[k * 32 + c]);

        ulonglong2* op = (ulonglong2*)(out + (size_t)h * SEQ_L + c * CHUNK);
#pragma unroll
        for (int k = 0; k < CHUNK / 4; k++)
            op[k] = make_ulonglong2(acc[2 * k], acc[2 * k + 1]);
    }
}

extern "C" void kernel_launch(void* const* d_in, const int* in_sizes, int n_in,
                              void* d_out, int out_size)
{
    const float* Cri   = (const float*)d_in[0];   // (1, H, N, 2)
    const float* logdt = (const float*)d_in[1];   // (H,)
    const float* Bri   = (const float*)d_in[2];   // (H, N, 2) (n_ssm == H)
    const float* invAr = (const float*)d_in[3];   // (H, N)
    const float* Aim   = (const float*)d_in[4];   // (H, N)
    float* out = (float*)d_out;                   // (1, H, L)

    ssk_fused<<<H_DIM, 128>>>(Cri, logdt, Bri, invAr, Aim, out);
}